// round 7
// baseline (speedup 1.0000x reference)
#include <cuda_runtime.h>
#include <cstdint>
#include <math.h>

#define BB 16
#define TT 2048
#define CC 768
#define HH 128

// Scratch for projected Q, K, V: [B][T][H] each.
// Stored ALREADY rna-rounded to tf32 (and Q pre-scaled), so the attention
// kernel can feed raw bits to tf32 mma with no further conversion.
__device__ float g_q[BB * TT * HH];
__device__ float g_k[BB * TT * HH];
__device__ float g_v[BB * TT * HH];

// ---------------------------------------------------------------------------
// helpers
// ---------------------------------------------------------------------------
__device__ __forceinline__ uint32_t f2tf(float f) {
    uint32_t u;
    asm("cvt.rna.tf32.f32 %0, %1;" : "=r"(u) : "f"(f));
    return u;
}

// D += A * B   (m16n8k8, tf32 inputs, fp32 accum)
__device__ __forceinline__ void mma8(float* d, const uint32_t* a, const uint32_t* b) {
    asm volatile(
        "mma.sync.aligned.m16n8k8.row.col.f32.tf32.tf32.f32 "
        "{%0,%1,%2,%3}, {%4,%5,%6,%7}, {%8,%9}, {%0,%1,%2,%3};"
        : "+f"(d[0]), "+f"(d[1]), "+f"(d[2]), "+f"(d[3])
        : "r"(a[0]), "r"(a[1]), "r"(a[2]), "r"(a[3]),
          "r"(b[0]), "r"(b[1]));
}

__device__ __forceinline__ void cp_async16(uint32_t smem_dst, const void* gmem_src) {
    asm volatile("cp.async.cg.shared.global [%0], [%1], 16;"
                 :: "r"(smem_dst), "l"(gmem_src) : "memory");
}
__device__ __forceinline__ void cp_async_commit() {
    asm volatile("cp.async.commit_group;" ::: "memory");
}
__device__ __forceinline__ void cp_async_wait_all() {
    asm volatile("cp.async.wait_group 0;" ::: "memory");
}

__device__ __forceinline__ uint32_t smem_u32(const void* p) {
    uint32_t a;
    asm("{ .reg .u64 t; cvta.to.shared.u64 t, %1; cvt.u32.u64 %0, t; }"
        : "=r"(a) : "l"(p));
    return a;
}

// ===========================================================================
// Kernel 1: fused QKV projection via mma.sync tf32.
// One CTA = 128 M-rows x ALL THREE weights. A staged + converted once,
// A-fragments reused across the 3 weights. Single smem buffer, bulk-sync.
// 256 threads, 8 warps: wr = wid&3 (32 rows), wc = wid>>2 (64 cols/weight).
// ===========================================================================
#define NCH 24   // 768 / 32

#define AS_STRIDE 36
#define BS_STRIDE 132
#define B_W_BUF (32 * BS_STRIDE)                    // per-weight B tile (words)
#define QKV_SMEM ((128 * AS_STRIDE + 3 * B_W_BUF) * 4)   // 69120 B

__global__ __launch_bounds__(256) void qkv_fused_kernel(
    const float* __restrict__ x,
    const float* __restrict__ Wq,
    const float* __restrict__ Wk,
    const float* __restrict__ Wv)
{
    extern __shared__ uint32_t sm_u[];
    uint32_t* As = sm_u;                       // [128][36]
    uint32_t* Bs = sm_u + 128 * AS_STRIDE;     // [3][32][132]

    const int tid  = threadIdx.x;
    const int wid  = tid >> 5;
    const int lane = tid & 31;
    const int g = lane >> 2;
    const int t = lane & 3;
    const int wr = wid & 3;      // 32-row group
    const int wc = wid >> 2;     // 64-col group (within each weight)
    const int m0 = blockIdx.x * 128;

    const float* Wptr[3] = {Wq, Wk, Wv};

    float acc[3][2][8][4];
    #pragma unroll
    for (int w = 0; w < 3; w++)
        #pragma unroll
        for (int mt = 0; mt < 2; mt++)
            #pragma unroll
            for (int nt = 0; nt < 8; nt++)
                #pragma unroll
                for (int e = 0; e < 4; e++) acc[w][mt][nt][e] = 0.0f;

    for (int c = 0; c < NCH; c++) {
        __syncthreads();   // previous compute done with smem

        // ---- stage A chunk: 128 rows x 32 k, tf32, vectorized STS ----
        {
            const float* xg = x + (size_t)m0 * CC + c * 32;
            #pragma unroll
            for (int p = 0; p < 4; p++) {
                int idx = tid + p * 256;          // 0..1023
                int m = idx >> 3, k4 = (idx & 7) << 2;
                float4 a = *reinterpret_cast<const float4*>(&xg[(size_t)m * CC + k4]);
                uint4 u;
                u.x = f2tf(a.x); u.y = f2tf(a.y);
                u.z = f2tf(a.z); u.w = f2tf(a.w);
                *reinterpret_cast<uint4*>(&As[m * AS_STRIDE + k4]) = u;
            }
        }
        // ---- stage B chunks: 3 x (32 k x 128 n), tf32 ----
        {
            #pragma unroll
            for (int p = 0; p < 12; p++) {
                int idx = tid + p * 256;          // 0..3071
                int w   = idx >> 10;
                int rem = idx & 1023;
                int k = rem >> 5, n4 = (rem & 31) << 2;
                const float* Wp = Wptr[w];
                float4 bv = *reinterpret_cast<const float4*>(
                    &Wp[(size_t)(c * 32 + k) * HH + n4]);
                const float ws = (w == 0) ? 0.03608439182435161f : 1.0f;
                uint4 u;
                u.x = f2tf(bv.x * ws); u.y = f2tf(bv.y * ws);
                u.z = f2tf(bv.z * ws); u.w = f2tf(bv.w * ws);
                *reinterpret_cast<uint4*>(&Bs[w * B_W_BUF + k * BS_STRIDE + n4]) = u;
            }
        }
        __syncthreads();

        // ---- compute: A-fragments shared across all 3 weights ----
        #pragma unroll
        for (int ks = 0; ks < 4; ks++) {
            const int k = ks * 8 + t;
            uint32_t afr[2][4];
            #pragma unroll
            for (int mt = 0; mt < 2; mt++) {
                int rbase = wr * 32 + mt * 16;
                afr[mt][0] = As[(rbase + g)     * AS_STRIDE + k];
                afr[mt][1] = As[(rbase + g + 8) * AS_STRIDE + k];
                afr[mt][2] = As[(rbase + g)     * AS_STRIDE + k + 4];
                afr[mt][3] = As[(rbase + g + 8) * AS_STRIDE + k + 4];
            }
            #pragma unroll
            for (int w = 0; w < 3; w++) {
                const uint32_t* Bw = Bs + w * B_W_BUF;
                #pragma unroll
                for (int nt = 0; nt < 8; nt++) {
                    const int n = wc * 64 + nt * 8 + g;
                    uint32_t bfr[2];
                    bfr[0] = Bw[k * BS_STRIDE + n];
                    bfr[1] = Bw[(k + 4) * BS_STRIDE + n];
                    mma8(acc[w][0][nt], afr[0], bfr);
                    mma8(acc[w][1][nt], afr[1], bfr);
                }
            }
        }
    }

    // ---- epilogue: store tf32-rounded bits ----
    float* outs[3] = {g_q, g_k, g_v};
    #pragma unroll
    for (int w = 0; w < 3; w++) {
        float* outw = outs[w];
        #pragma unroll
        for (int mt = 0; mt < 2; mt++) {
            int r0 = m0 + wr * 32 + mt * 16 + g;
            #pragma unroll
            for (int nt = 0; nt < 8; nt++) {
                int col = wc * 64 + nt * 8 + 2 * t;
                *reinterpret_cast<float2*>(&outw[(size_t)r0 * HH + col]) =
                    make_float2(__uint_as_float(f2tf(acc[w][mt][nt][0])),
                                __uint_as_float(f2tf(acc[w][mt][nt][1])));
                *reinterpret_cast<float2*>(&outw[(size_t)(r0 + 8) * HH + col]) =
                    make_float2(__uint_as_float(f2tf(acc[w][mt][nt][2])),
                                __uint_as_float(f2tf(acc[w][mt][nt][3])));
            }
        }
    }
}

// ===========================================================================
// Kernel 2: register-resident causal flash attention with cp.async pipeline
// (unchanged from R6 — known good at 170.9 us).
// ===========================================================================
#define KS_STRIDE 132
#define VS_STRIDE 136
#define ATTN_SMEM ((64 * KS_STRIDE + 64 * VS_STRIDE) * 4)   // 68608 B

__global__ __launch_bounds__(128, 2) void attn_fa2_kernel(float* __restrict__ out)
{
    extern __shared__ float smf[];
    float* Ks = smf;                     // [64][132]
    float* Vs = Ks + 64 * KS_STRIDE;     // [64][136]  (also Q staging)
    uint32_t* Ksu = reinterpret_cast<uint32_t*>(Ks);
    uint32_t* Vsu = reinterpret_cast<uint32_t*>(Vs);
    const uint32_t Ks_a = smem_u32(Ks);
    const uint32_t Vs_a = smem_u32(Vs);

    const int b  = blockIdx.y;
    const int qt = (int)gridDim.x - 1 - (int)blockIdx.x;   // heavy tiles first
    const int q0 = qt * 64;
    const int tid  = threadIdx.x;
    const int wid  = tid >> 5;
    const int lane = tid & 31;
    const int g = lane >> 2;
    const int t = lane & 3;

    const int r0l = wid * 16 + g;
    const int r1l = r0l + 8;

    const float* kbase = g_k + (size_t)b * TT * HH;
    const float* vbase = g_v + (size_t)b * TT * HH;

    // ---- prologue: start K[0] async load; stage Q through Vs ----
    {
        const float* kg = kbase;
        #pragma unroll
        for (int p = 0; p < 16; p++) {
            int idx = tid + p * 128;
            int r = idx >> 5, c = (idx & 31) << 2;
            cp_async16(Ks_a + (uint32_t)(r * KS_STRIDE + c) * 4,
                       kg + (size_t)r * HH + c);
        }
        cp_async_commit();
    }
    {
        const float* qg = g_q + ((size_t)b * TT + q0) * HH;
        #pragma unroll
        for (int p = 0; p < 16; p++) {
            int idx = tid + p * 128;
            int r = idx >> 5, c4 = (idx & 31) << 2;
            *reinterpret_cast<float4*>(&Vs[r * VS_STRIDE + c4]) =
                *reinterpret_cast<const float4*>(&qg[(size_t)r * HH + c4]);
        }
    }
    __syncthreads();

    uint32_t qfr[16][4];
    #pragma unroll
    for (int ks = 0; ks < 16; ks++) {
        const int k = ks * 8 + t;
        qfr[ks][0] = Vsu[r0l * VS_STRIDE + k];
        qfr[ks][1] = Vsu[r1l * VS_STRIDE + k];
        qfr[ks][2] = Vsu[r0l * VS_STRIDE + k + 4];
        qfr[ks][3] = Vsu[r1l * VS_STRIDE + k + 4];
    }

    float m0 = -INFINITY, m1 = -INFINITY, l0 = 0.0f, l1 = 0.0f;
    float oacc[16][4];
    #pragma unroll
    for (int nt = 0; nt < 16; nt++)
        #pragma unroll
        for (int e = 0; e < 4; e++) oacc[nt][e] = 0.0f;

    const uint32_t srcA = (lane & 28) | (t >> 1);
    const uint32_t srcB = srcA + 2;

    const int nkt = qt + 1;
    for (int kt = 0; kt < nkt; kt++) {
        cp_async_wait_all();
        __syncthreads();

        // ---- start V[kt] load (overlaps S compute) ----
        {
            const float* vg = vbase + (size_t)kt * 64 * HH;
            #pragma unroll
            for (int p = 0; p < 16; p++) {
                int idx = tid + p * 128;
                int r = idx >> 5, c = (idx & 31) << 2;
                cp_async16(Vs_a + (uint32_t)(r * VS_STRIDE + c) * 4,
                           vg + (size_t)r * HH + c);
            }
            cp_async_commit();
        }

        // ---- S = Q K^T ----
        float sacc[8][4];
        #pragma unroll
        for (int nt = 0; nt < 8; nt++)
            #pragma unroll
            for (int e = 0; e < 4; e++) sacc[nt][e] = 0.0f;

        #pragma unroll
        for (int ks = 0; ks < 16; ks++) {
            const int k = ks * 8 + t;
            #pragma unroll
            for (int nt = 0; nt < 8; nt++) {
                const int n = nt * 8 + g;
                uint32_t bfr[2];
                bfr[0] = Ksu[n * KS_STRIDE + k];
                bfr[1] = Ksu[n * KS_STRIDE + k + 4];
                mma8(sacc[nt], qfr[ks], bfr);
            }
        }

        if (kt == qt) {
            #pragma unroll
            for (int nt = 0; nt < 8; nt++) {
                const int cl = nt * 8 + 2 * t;
                if (cl     > r0l) sacc[nt][0] = -INFINITY;
                if (cl + 1 > r0l) sacc[nt][1] = -INFINITY;
                if (cl     > r1l) sacc[nt][2] = -INFINITY;
                if (cl + 1 > r1l) sacc[nt][3] = -INFINITY;
            }
        }

        // ---- online softmax in registers ----
        float mx0 = -INFINITY, mx1 = -INFINITY;
        #pragma unroll
        for (int nt = 0; nt < 8; nt++) {
            mx0 = fmaxf(mx0, fmaxf(sacc[nt][0], sacc[nt][1]));
            mx1 = fmaxf(mx1, fmaxf(sacc[nt][2], sacc[nt][3]));
        }
        mx0 = fmaxf(mx0, __shfl_xor_sync(0xffffffffu, mx0, 1));
        mx0 = fmaxf(mx0, __shfl_xor_sync(0xffffffffu, mx0, 2));
        mx1 = fmaxf(mx1, __shfl_xor_sync(0xffffffffu, mx1, 1));
        mx1 = fmaxf(mx1, __shfl_xor_sync(0xffffffffu, mx1, 2));

        const float m0n = fmaxf(m0, mx0);
        const float m1n = fmaxf(m1, mx1);
        const float c0 = __expf(m0 - m0n);
        const float c1 = __expf(m1 - m1n);

        float s0 = 0.0f, s1 = 0.0f;
        #pragma unroll
        for (int nt = 0; nt < 8; nt++) {
            sacc[nt][0] = __expf(sacc[nt][0] - m0n);
            sacc[nt][1] = __expf(sacc[nt][1] - m0n);
            sacc[nt][2] = __expf(sacc[nt][2] - m1n);
            sacc[nt][3] = __expf(sacc[nt][3] - m1n);
            s0 += sacc[nt][0] + sacc[nt][1];
            s1 += sacc[nt][2] + sacc[nt][3];
        }
        s0 += __shfl_xor_sync(0xffffffffu, s0, 1);
        s0 += __shfl_xor_sync(0xffffffffu, s0, 2);
        s1 += __shfl_xor_sync(0xffffffffu, s1, 1);
        s1 += __shfl_xor_sync(0xffffffffu, s1, 2);

        l0 = l0 * c0 + s0;
        l1 = l1 * c1 + s1;
        m0 = m0n;
        m1 = m1n;

        #pragma unroll
        for (int nt = 0; nt < 16; nt++) {
            oacc[nt][0] *= c0; oacc[nt][1] *= c0;
            oacc[nt][2] *= c1; oacc[nt][3] *= c1;
        }

        cp_async_wait_all();
        __syncthreads();

        // ---- start K[kt+1] load (overlaps PV compute) ----
        if (kt + 1 < nkt) {
            const float* kg = kbase + (size_t)(kt + 1) * 64 * HH;
            #pragma unroll
            for (int p = 0; p < 16; p++) {
                int idx = tid + p * 128;
                int r = idx >> 5, c = (idx & 31) << 2;
                cp_async16(Ks_a + (uint32_t)(r * KS_STRIDE + c) * 4,
                           kg + (size_t)r * HH + c);
            }
            cp_async_commit();
        }

        // ---- O += P V : P from registers via quad shuffles ----
        #pragma unroll
        for (int kk = 0; kk < 8; kk++) {
            float v0 = __shfl_sync(0xffffffffu, sacc[kk][0], srcA);
            float v1 = __shfl_sync(0xffffffffu, sacc[kk][1], srcA);
            float v2 = __shfl_sync(0xffffffffu, sacc[kk][2], srcA);
            float v3 = __shfl_sync(0xffffffffu, sacc[kk][3], srcA);
            float w0 = __shfl_sync(0xffffffffu, sacc[kk][0], srcB);
            float w1 = __shfl_sync(0xffffffffu, sacc[kk][1], srcB);
            float w2 = __shfl_sync(0xffffffffu, sacc[kk][2], srcB);
            float w3 = __shfl_sync(0xffffffffu, sacc[kk][3], srcB);
            uint32_t afr[4];
            afr[0] = f2tf((t & 1) ? v1 : v0);
            afr[1] = f2tf((t & 1) ? v3 : v2);
            afr[2] = f2tf((t & 1) ? w1 : w0);
            afr[3] = f2tf((t & 1) ? w3 : w2);

            const int k = kk * 8 + t;
            #pragma unroll
            for (int nt = 0; nt < 16; nt++) {
                const int n = nt * 8 + g;
                uint32_t bfr[2];
                bfr[0] = Vsu[k * VS_STRIDE + n];
                bfr[1] = Vsu[(k + 4) * VS_STRIDE + n];
                mma8(oacc[nt], afr, bfr);
            }
        }
    }

    // ---- epilogue ----
    const float inv0 = 1.0f / l0;
    const float inv1 = 1.0f / l1;
    float* og = out + ((size_t)b * TT + q0) * HH;
    #pragma unroll
    for (int nt = 0; nt < 16; nt++) {
        const int col = nt * 8 + 2 * t;
        *reinterpret_cast<float2*>(&og[(size_t)r0l * HH + col]) =
            make_float2(oacc[nt][0] * inv0, oacc[nt][1] * inv0);
        *reinterpret_cast<float2*>(&og[(size_t)r1l * HH + col]) =
            make_float2(oacc[nt][2] * inv1, oacc[nt][3] * inv1);
    }
}

// ===========================================================================
// Launch
// ===========================================================================
extern "C" void kernel_launch(void* const* d_in, const int* in_sizes, int n_in,
                              void* d_out, int out_size)
{
    const float* x  = (const float*)d_in[0];
    const float* Wq = (const float*)d_in[1];
    const float* Wk = (const float*)d_in[2];
    const float* Wv = (const float*)d_in[3];
    float* out = (float*)d_out;

    cudaFuncSetAttribute(qkv_fused_kernel,
                         cudaFuncAttributeMaxDynamicSharedMemorySize, QKV_SMEM);
    cudaFuncSetAttribute(attn_fa2_kernel,
                         cudaFuncAttributeMaxDynamicSharedMemorySize, ATTN_SMEM);

    // fused QKV: one CTA per 128 M-rows, all three weights
    qkv_fused_kernel<<<TT * BB / 128, 256, QKV_SMEM>>>(x, Wq, Wk, Wv);
    attn_fa2_kernel<<<dim3(TT / 64, BB), 128, ATTN_SMEM>>>(out);
}

// round 8
// speedup vs baseline: 1.0239x; 1.0239x over previous
#include <cuda_runtime.h>
#include <cstdint>
#include <math.h>

#define BB 16
#define TT 2048
#define CC 768
#define HH 128

// Pre-converted inputs (tf32-rounded bits stored as float)
__device__ float g_x[BB * TT * CC];          // x, rna tf32
__device__ float g_w[3 * CC * HH];           // Wq(scaled)/Wk/Wv, rna tf32
// Projected Q, K, V (tf32-rounded, Q pre-scaled)
__device__ float g_q[BB * TT * HH];
__device__ float g_k[BB * TT * HH];
__device__ float g_v[BB * TT * HH];

// ---------------------------------------------------------------------------
// helpers
// ---------------------------------------------------------------------------
__device__ __forceinline__ uint32_t f2tf(float f) {
    uint32_t u;
    asm("cvt.rna.tf32.f32 %0, %1;" : "=r"(u) : "f"(f));
    return u;
}

__device__ __forceinline__ void mma8(float* d, const uint32_t* a, const uint32_t* b) {
    asm volatile(
        "mma.sync.aligned.m16n8k8.row.col.f32.tf32.tf32.f32 "
        "{%0,%1,%2,%3}, {%4,%5,%6,%7}, {%8,%9}, {%0,%1,%2,%3};"
        : "+f"(d[0]), "+f"(d[1]), "+f"(d[2]), "+f"(d[3])
        : "r"(a[0]), "r"(a[1]), "r"(a[2]), "r"(a[3]),
          "r"(b[0]), "r"(b[1]));
}

__device__ __forceinline__ void cp_async16(uint32_t smem_dst, const void* gmem_src) {
    asm volatile("cp.async.cg.shared.global [%0], [%1], 16;"
                 :: "r"(smem_dst), "l"(gmem_src) : "memory");
}
__device__ __forceinline__ void cp_async_commit() {
    asm volatile("cp.async.commit_group;" ::: "memory");
}
__device__ __forceinline__ void cp_async_wait_all() {
    asm volatile("cp.async.wait_group 0;" ::: "memory");
}
__device__ __forceinline__ void cp_async_wait_1() {
    asm volatile("cp.async.wait_group 1;" ::: "memory");
}

__device__ __forceinline__ uint32_t smem_u32(const void* p) {
    uint32_t a;
    asm("{ .reg .u64 t; cvta.to.shared.u64 t, %1; cvt.u32.u64 %0, t; }"
        : "=r"(a) : "l"(p));
    return a;
}

// ===========================================================================
// Kernel 0a/0b: pre-convert x and W to tf32 bits (Wq pre-scaled).
// ===========================================================================
__global__ __launch_bounds__(256) void conv_x_kernel(const float* __restrict__ x)
{
    const int n4 = BB * TT * CC / 4;
    for (int i = blockIdx.x * blockDim.x + threadIdx.x; i < n4;
         i += gridDim.x * blockDim.x) {
        float4 v = reinterpret_cast<const float4*>(x)[i];
        uint4 u;
        u.x = f2tf(v.x); u.y = f2tf(v.y); u.z = f2tf(v.z); u.w = f2tf(v.w);
        reinterpret_cast<uint4*>(g_x)[i] = u;
    }
}

__global__ __launch_bounds__(256) void conv_w_kernel(
    const float* __restrict__ Wq,
    const float* __restrict__ Wk,
    const float* __restrict__ Wv)
{
    const int per = CC * HH / 4;     // float4 per weight
    const float* Ws[3] = {Wq, Wk, Wv};
    for (int i = blockIdx.x * blockDim.x + threadIdx.x; i < 3 * per;
         i += gridDim.x * blockDim.x) {
        int w = i / per, j = i - w * per;
        float s = (w == 0) ? 0.03608439182435161f : 1.0f;
        float4 v = reinterpret_cast<const float4*>(Ws[w])[j];
        uint4 u;
        u.x = f2tf(v.x * s); u.y = f2tf(v.y * s);
        u.z = f2tf(v.z * s); u.w = f2tf(v.w * s);
        reinterpret_cast<uint4*>(g_w)[w * per + j] = u;
    }
}

// ===========================================================================
// Kernel 1: fused QKV projection, 2-stage cp.async pipeline, zero cvt.
// One CTA = 128 M-rows x all three weights; A-fragments reused 3x.
// 256 threads, 8 warps: wr = wid&3 (32 rows), wc = wid>>2 (64 cols/weight).
// ===========================================================================
#define NCH 24   // 768 / 32

#define AS_STRIDE 36
#define BS_STRIDE 132
#define A_BUF (128 * AS_STRIDE)                  // words, per stage
#define B_W_BUF (32 * BS_STRIDE)                 // words, per weight
#define STAGE_WORDS (A_BUF + 3 * B_W_BUF)        // 17280 words
#define QKV_SMEM (2 * STAGE_WORDS * 4)           // 138240 B

__global__ __launch_bounds__(256) void qkv_fused_kernel()
{
    extern __shared__ uint32_t sm_u[];
    const uint32_t sm_a = smem_u32(sm_u);

    const int tid  = threadIdx.x;
    const int wid  = tid >> 5;
    const int lane = tid & 31;
    const int g = lane >> 2;
    const int t = lane & 3;
    const int wr = wid & 3;
    const int wc = wid >> 2;
    const int m0 = blockIdx.x * 128;

    float acc[3][2][8][4];
    #pragma unroll
    for (int w = 0; w < 3; w++)
        #pragma unroll
        for (int mt = 0; mt < 2; mt++)
            #pragma unroll
            for (int nt = 0; nt < 8; nt++)
                #pragma unroll
                for (int e = 0; e < 4; e++) acc[w][mt][nt][e] = 0.0f;

    // issue cp.async for chunk c into stage buffer
    auto issue_stage = [&](int c, int buf) {
        const uint32_t base = sm_a + (uint32_t)buf * STAGE_WORDS * 4;
        // A: 128 x 32 = 1024 float4 chunks
        const float* xg = g_x + (size_t)m0 * CC + c * 32;
        #pragma unroll
        for (int p = 0; p < 4; p++) {
            int idx = tid + p * 256;
            int m = idx >> 3, k4 = (idx & 7) << 2;
            cp_async16(base + (uint32_t)(m * AS_STRIDE + k4) * 4,
                       xg + (size_t)m * CC + k4);
        }
        // B: 3 x 32 x 128 = 3072 float4 chunks
        #pragma unroll
        for (int p = 0; p < 12; p++) {
            int idx = tid + p * 256;
            int w = idx >> 10;
            int rem = idx & 1023;
            int k = rem >> 5, n4 = (rem & 31) << 2;
            cp_async16(base + (uint32_t)(A_BUF + w * B_W_BUF + k * BS_STRIDE + n4) * 4,
                       g_w + (size_t)w * CC * HH + (size_t)(c * 32 + k) * HH + n4);
        }
        cp_async_commit();
    };

    issue_stage(0, 0);

    for (int c = 0; c < NCH; c++) {
        const int buf = c & 1;
        // all warps done computing on buffer (c+1)&1 from iteration c-1
        __syncthreads();
        if (c + 1 < NCH) {
            issue_stage(c + 1, buf ^ 1);
            cp_async_wait_1();     // chunk c complete, c+1 may be in flight
        } else {
            cp_async_wait_all();
        }
        __syncthreads();

        const uint32_t* As = sm_u + buf * STAGE_WORDS;
        const uint32_t* Bs = As + A_BUF;

        #pragma unroll
        for (int ks = 0; ks < 4; ks++) {
            const int k = ks * 8 + t;
            uint32_t afr[2][4];
            #pragma unroll
            for (int mt = 0; mt < 2; mt++) {
                int rbase = wr * 32 + mt * 16;
                afr[mt][0] = As[(rbase + g)     * AS_STRIDE + k];
                afr[mt][1] = As[(rbase + g + 8) * AS_STRIDE + k];
                afr[mt][2] = As[(rbase + g)     * AS_STRIDE + k + 4];
                afr[mt][3] = As[(rbase + g + 8) * AS_STRIDE + k + 4];
            }
            #pragma unroll
            for (int w = 0; w < 3; w++) {
                const uint32_t* Bw = Bs + w * B_W_BUF;
                #pragma unroll
                for (int nt = 0; nt < 8; nt++) {
                    const int n = wc * 64 + nt * 8 + g;
                    uint32_t bfr[2];
                    bfr[0] = Bw[k * BS_STRIDE + n];
                    bfr[1] = Bw[(k + 4) * BS_STRIDE + n];
                    mma8(acc[w][0][nt], afr[0], bfr);
                    mma8(acc[w][1][nt], afr[1], bfr);
                }
            }
        }
    }

    // ---- epilogue: store tf32-rounded bits ----
    float* outs[3] = {g_q, g_k, g_v};
    #pragma unroll
    for (int w = 0; w < 3; w++) {
        float* outw = outs[w];
        #pragma unroll
        for (int mt = 0; mt < 2; mt++) {
            int r0 = m0 + wr * 32 + mt * 16 + g;
            #pragma unroll
            for (int nt = 0; nt < 8; nt++) {
                int col = wc * 64 + nt * 8 + 2 * t;
                *reinterpret_cast<float2*>(&outw[(size_t)r0 * HH + col]) =
                    make_float2(__uint_as_float(f2tf(acc[w][mt][nt][0])),
                                __uint_as_float(f2tf(acc[w][mt][nt][1])));
                *reinterpret_cast<float2*>(&outw[(size_t)(r0 + 8) * HH + col]) =
                    make_float2(__uint_as_float(f2tf(acc[w][mt][nt][2])),
                                __uint_as_float(f2tf(acc[w][mt][nt][3])));
            }
        }
    }
}

// ===========================================================================
// Kernel 2: register-resident causal flash attention with cp.async pipeline
// (unchanged — known good at ~169 us).
// ===========================================================================
#define KS_STRIDE 132
#define VS_STRIDE 136
#define ATTN_SMEM ((64 * KS_STRIDE + 64 * VS_STRIDE) * 4)   // 68608 B

__global__ __launch_bounds__(128, 2) void attn_fa2_kernel(float* __restrict__ out)
{
    extern __shared__ float smf[];
    float* Ks = smf;                     // [64][132]
    float* Vs = Ks + 64 * KS_STRIDE;     // [64][136]  (also Q staging)
    uint32_t* Ksu = reinterpret_cast<uint32_t*>(Ks);
    uint32_t* Vsu = reinterpret_cast<uint32_t*>(Vs);
    const uint32_t Ks_a = smem_u32(Ks);
    const uint32_t Vs_a = smem_u32(Vs);

    const int b  = blockIdx.y;
    const int qt = (int)gridDim.x - 1 - (int)blockIdx.x;
    const int q0 = qt * 64;
    const int tid  = threadIdx.x;
    const int wid  = tid >> 5;
    const int lane = tid & 31;
    const int g = lane >> 2;
    const int t = lane & 3;

    const int r0l = wid * 16 + g;
    const int r1l = r0l + 8;

    const float* kbase = g_k + (size_t)b * TT * HH;
    const float* vbase = g_v + (size_t)b * TT * HH;

    {
        const float* kg = kbase;
        #pragma unroll
        for (int p = 0; p < 16; p++) {
            int idx = tid + p * 128;
            int r = idx >> 5, c = (idx & 31) << 2;
            cp_async16(Ks_a + (uint32_t)(r * KS_STRIDE + c) * 4,
                       kg + (size_t)r * HH + c);
        }
        cp_async_commit();
    }
    {
        const float* qg = g_q + ((size_t)b * TT + q0) * HH;
        #pragma unroll
        for (int p = 0; p < 16; p++) {
            int idx = tid + p * 128;
            int r = idx >> 5, c4 = (idx & 31) << 2;
            *reinterpret_cast<float4*>(&Vs[r * VS_STRIDE + c4]) =
                *reinterpret_cast<const float4*>(&qg[(size_t)r * HH + c4]);
        }
    }
    __syncthreads();

    uint32_t qfr[16][4];
    #pragma unroll
    for (int ks = 0; ks < 16; ks++) {
        const int k = ks * 8 + t;
        qfr[ks][0] = Vsu[r0l * VS_STRIDE + k];
        qfr[ks][1] = Vsu[r1l * VS_STRIDE + k];
        qfr[ks][2] = Vsu[r0l * VS_STRIDE + k + 4];
        qfr[ks][3] = Vsu[r1l * VS_STRIDE + k + 4];
    }

    float m0 = -INFINITY, m1 = -INFINITY, l0 = 0.0f, l1 = 0.0f;
    float oacc[16][4];
    #pragma unroll
    for (int nt = 0; nt < 16; nt++)
        #pragma unroll
        for (int e = 0; e < 4; e++) oacc[nt][e] = 0.0f;

    const uint32_t srcA = (lane & 28) | (t >> 1);
    const uint32_t srcB = srcA + 2;

    const int nkt = qt + 1;
    for (int kt = 0; kt < nkt; kt++) {
        cp_async_wait_all();
        __syncthreads();

        {
            const float* vg = vbase + (size_t)kt * 64 * HH;
            #pragma unroll
            for (int p = 0; p < 16; p++) {
                int idx = tid + p * 128;
                int r = idx >> 5, c = (idx & 31) << 2;
                cp_async16(Vs_a + (uint32_t)(r * VS_STRIDE + c) * 4,
                           vg + (size_t)r * HH + c);
            }
            cp_async_commit();
        }

        float sacc[8][4];
        #pragma unroll
        for (int nt = 0; nt < 8; nt++)
            #pragma unroll
            for (int e = 0; e < 4; e++) sacc[nt][e] = 0.0f;

        #pragma unroll
        for (int ks = 0; ks < 16; ks++) {
            const int k = ks * 8 + t;
            #pragma unroll
            for (int nt = 0; nt < 8; nt++) {
                const int n = nt * 8 + g;
                uint32_t bfr[2];
                bfr[0] = Ksu[n * KS_STRIDE + k];
                bfr[1] = Ksu[n * KS_STRIDE + k + 4];
                mma8(sacc[nt], qfr[ks], bfr);
            }
        }

        if (kt == qt) {
            #pragma unroll
            for (int nt = 0; nt < 8; nt++) {
                const int cl = nt * 8 + 2 * t;
                if (cl     > r0l) sacc[nt][0] = -INFINITY;
                if (cl + 1 > r0l) sacc[nt][1] = -INFINITY;
                if (cl     > r1l) sacc[nt][2] = -INFINITY;
                if (cl + 1 > r1l) sacc[nt][3] = -INFINITY;
            }
        }

        float mx0 = -INFINITY, mx1 = -INFINITY;
        #pragma unroll
        for (int nt = 0; nt < 8; nt++) {
            mx0 = fmaxf(mx0, fmaxf(sacc[nt][0], sacc[nt][1]));
            mx1 = fmaxf(mx1, fmaxf(sacc[nt][2], sacc[nt][3]));
        }
        mx0 = fmaxf(mx0, __shfl_xor_sync(0xffffffffu, mx0, 1));
        mx0 = fmaxf(mx0, __shfl_xor_sync(0xffffffffu, mx0, 2));
        mx1 = fmaxf(mx1, __shfl_xor_sync(0xffffffffu, mx1, 1));
        mx1 = fmaxf(mx1, __shfl_xor_sync(0xffffffffu, mx1, 2));

        const float m0n = fmaxf(m0, mx0);
        const float m1n = fmaxf(m1, mx1);
        const float c0 = __expf(m0 - m0n);
        const float c1 = __expf(m1 - m1n);

        float s0 = 0.0f, s1 = 0.0f;
        #pragma unroll
        for (int nt = 0; nt < 8; nt++) {
            sacc[nt][0] = __expf(sacc[nt][0] - m0n);
            sacc[nt][1] = __expf(sacc[nt][1] - m0n);
            sacc[nt][2] = __expf(sacc[nt][2] - m1n);
            sacc[nt][3] = __expf(sacc[nt][3] - m1n);
            s0 += sacc[nt][0] + sacc[nt][1];
            s1 += sacc[nt][2] + sacc[nt][3];
        }
        s0 += __shfl_xor_sync(0xffffffffu, s0, 1);
        s0 += __shfl_xor_sync(0xffffffffu, s0, 2);
        s1 += __shfl_xor_sync(0xffffffffu, s1, 1);
        s1 += __shfl_xor_sync(0xffffffffu, s1, 2);

        l0 = l0 * c0 + s0;
        l1 = l1 * c1 + s1;
        m0 = m0n;
        m1 = m1n;

        #pragma unroll
        for (int nt = 0; nt < 16; nt++) {
            oacc[nt][0] *= c0; oacc[nt][1] *= c0;
            oacc[nt][2] *= c1; oacc[nt][3] *= c1;
        }

        cp_async_wait_all();
        __syncthreads();

        if (kt + 1 < nkt) {
            const float* kg = kbase + (size_t)(kt + 1) * 64 * HH;
            #pragma unroll
            for (int p = 0; p < 16; p++) {
                int idx = tid + p * 128;
                int r = idx >> 5, c = (idx & 31) << 2;
                cp_async16(Ks_a + (uint32_t)(r * KS_STRIDE + c) * 4,
                           kg + (size_t)r * HH + c);
            }
            cp_async_commit();
        }

        #pragma unroll
        for (int kk = 0; kk < 8; kk++) {
            float v0 = __shfl_sync(0xffffffffu, sacc[kk][0], srcA);
            float v1 = __shfl_sync(0xffffffffu, sacc[kk][1], srcA);
            float v2 = __shfl_sync(0xffffffffu, sacc[kk][2], srcA);
            float v3 = __shfl_sync(0xffffffffu, sacc[kk][3], srcA);
            float w0 = __shfl_sync(0xffffffffu, sacc[kk][0], srcB);
            float w1 = __shfl_sync(0xffffffffu, sacc[kk][1], srcB);
            float w2 = __shfl_sync(0xffffffffu, sacc[kk][2], srcB);
            float w3 = __shfl_sync(0xffffffffu, sacc[kk][3], srcB);
            uint32_t afr[4];
            afr[0] = f2tf((t & 1) ? v1 : v0);
            afr[1] = f2tf((t & 1) ? v3 : v2);
            afr[2] = f2tf((t & 1) ? w1 : w0);
            afr[3] = f2tf((t & 1) ? w3 : w2);

            const int k = kk * 8 + t;
            #pragma unroll
            for (int nt = 0; nt < 16; nt++) {
                const int n = nt * 8 + g;
                uint32_t bfr[2];
                bfr[0] = Vsu[k * VS_STRIDE + n];
                bfr[1] = Vsu[(k + 4) * VS_STRIDE + n];
                mma8(oacc[nt], afr, bfr);
            }
        }
    }

    const float inv0 = 1.0f / l0;
    const float inv1 = 1.0f / l1;
    float* og = out + ((size_t)b * TT + q0) * HH;
    #pragma unroll
    for (int nt = 0; nt < 16; nt++) {
        const int col = nt * 8 + 2 * t;
        *reinterpret_cast<float2*>(&og[(size_t)r0l * HH + col]) =
            make_float2(oacc[nt][0] * inv0, oacc[nt][1] * inv0);
        *reinterpret_cast<float2*>(&og[(size_t)r1l * HH + col]) =
            make_float2(oacc[nt][2] * inv1, oacc[nt][3] * inv1);
    }
}

// ===========================================================================
// Launch
// ===========================================================================
extern "C" void kernel_launch(void* const* d_in, const int* in_sizes, int n_in,
                              void* d_out, int out_size)
{
    const float* x  = (const float*)d_in[0];
    const float* Wq = (const float*)d_in[1];
    const float* Wk = (const float*)d_in[2];
    const float* Wv = (const float*)d_in[3];
    float* out = (float*)d_out;

    cudaFuncSetAttribute(qkv_fused_kernel,
                         cudaFuncAttributeMaxDynamicSharedMemorySize, QKV_SMEM);
    cudaFuncSetAttribute(attn_fa2_kernel,
                         cudaFuncAttributeMaxDynamicSharedMemorySize, ATTN_SMEM);

    conv_x_kernel<<<2048, 256>>>(x);
    conv_w_kernel<<<96, 256>>>(Wq, Wk, Wv);
    qkv_fused_kernel<<<TT * BB / 128, 256, QKV_SMEM>>>();
    attn_fa2_kernel<<<dim3(TT / 64, BB), 128, ATTN_SMEM>>>(out);
}

// round 9
// speedup vs baseline: 1.1272x; 1.1009x over previous
#include <cuda_runtime.h>
#include <cstdint>
#include <math.h>

#define BB 16
#define TT 2048
#define CC 768
#define HH 128

// Pre-converted weights (tf32-rounded bits stored as float; Wq pre-scaled)
__device__ float g_w[3 * CC * HH];
// Projected Q, K, V (tf32-rounded, Q pre-scaled)
__device__ float g_q[BB * TT * HH];
__device__ float g_k[BB * TT * HH];
__device__ float g_v[BB * TT * HH];

// ---------------------------------------------------------------------------
// helpers
// ---------------------------------------------------------------------------
__device__ __forceinline__ uint32_t f2tf(float f) {
    uint32_t u;
    asm("cvt.rna.tf32.f32 %0, %1;" : "=r"(u) : "f"(f));
    return u;
}

__device__ __forceinline__ void mma8(float* d, const uint32_t* a, const uint32_t* b) {
    asm volatile(
        "mma.sync.aligned.m16n8k8.row.col.f32.tf32.tf32.f32 "
        "{%0,%1,%2,%3}, {%4,%5,%6,%7}, {%8,%9}, {%0,%1,%2,%3};"
        : "+f"(d[0]), "+f"(d[1]), "+f"(d[2]), "+f"(d[3])
        : "r"(a[0]), "r"(a[1]), "r"(a[2]), "r"(a[3]),
          "r"(b[0]), "r"(b[1]));
}

__device__ __forceinline__ void cp_async16(uint32_t smem_dst, const void* gmem_src) {
    asm volatile("cp.async.cg.shared.global [%0], [%1], 16;"
                 :: "r"(smem_dst), "l"(gmem_src) : "memory");
}
__device__ __forceinline__ void cp_async_commit() {
    asm volatile("cp.async.commit_group;" ::: "memory");
}
__device__ __forceinline__ void cp_async_wait_all() {
    asm volatile("cp.async.wait_group 0;" ::: "memory");
}
__device__ __forceinline__ void cp_async_wait_1() {
    asm volatile("cp.async.wait_group 1;" ::: "memory");
}

__device__ __forceinline__ uint32_t smem_u32(const void* p) {
    uint32_t a;
    asm("{ .reg .u64 t; cvta.to.shared.u64 t, %1; cvt.u32.u64 %0, t; }"
        : "=r"(a) : "l"(p));
    return a;
}

// ===========================================================================
// Kernel 0: pre-convert W to tf32 bits (Wq pre-scaled). 0.4 MB total.
// x is NOT pre-converted: the tf32 mma hardware truncates raw fp32 bits,
// which costs ~1e-4 extra rel err but saves a 200 MB conversion pass.
// ===========================================================================
__global__ __launch_bounds__(256) void conv_w_kernel(
    const float* __restrict__ Wq,
    const float* __restrict__ Wk,
    const float* __restrict__ Wv)
{
    const int per = CC * HH / 4;     // float4 per weight
    const float* Ws[3] = {Wq, Wk, Wv};
    for (int i = blockIdx.x * blockDim.x + threadIdx.x; i < 3 * per;
         i += gridDim.x * blockDim.x) {
        int w = i / per, j = i - w * per;
        float s = (w == 0) ? 0.03608439182435161f : 1.0f;
        float4 v = reinterpret_cast<const float4*>(Ws[w])[j];
        uint4 u;
        u.x = f2tf(v.x * s); u.y = f2tf(v.y * s);
        u.z = f2tf(v.z * s); u.w = f2tf(v.w * s);
        reinterpret_cast<uint4*>(g_w)[w * per + j] = u;
    }
}

// ===========================================================================
// Kernel 1: fused QKV projection, 2-stage cp.async pipeline, zero cvt.
// A (raw x) staged once per chunk; A-fragments reused across all 3 weights.
// 256 threads, 8 warps: wr = wid&3 (32 rows), wc = wid>>2 (64 cols/weight).
// ===========================================================================
#define NCH 24   // 768 / 32

#define AS_STRIDE 36
#define BS_STRIDE 132
#define A_BUF (128 * AS_STRIDE)                  // words, per stage
#define B_W_BUF (32 * BS_STRIDE)                 // words, per weight
#define STAGE_WORDS (A_BUF + 3 * B_W_BUF)        // 17280 words
#define QKV_SMEM (2 * STAGE_WORDS * 4)           // 138240 B

__global__ __launch_bounds__(256) void qkv_fused_kernel(const float* __restrict__ x)
{
    extern __shared__ uint32_t sm_u[];
    const uint32_t sm_a = smem_u32(sm_u);

    const int tid  = threadIdx.x;
    const int wid  = tid >> 5;
    const int lane = tid & 31;
    const int g = lane >> 2;
    const int t = lane & 3;
    const int wr = wid & 3;
    const int wc = wid >> 2;
    const int m0 = blockIdx.x * 128;

    float acc[3][2][8][4];
    #pragma unroll
    for (int w = 0; w < 3; w++)
        #pragma unroll
        for (int mt = 0; mt < 2; mt++)
            #pragma unroll
            for (int nt = 0; nt < 8; nt++)
                #pragma unroll
                for (int e = 0; e < 4; e++) acc[w][mt][nt][e] = 0.0f;

    auto issue_stage = [&](int c, int buf) {
        const uint32_t base = sm_a + (uint32_t)buf * STAGE_WORDS * 4;
        // A: 128 x 32 raw fp32 (HW truncates to tf32 inside mma)
        const float* xg = x + (size_t)m0 * CC + c * 32;
        #pragma unroll
        for (int p = 0; p < 4; p++) {
            int idx = tid + p * 256;
            int m = idx >> 3, k4 = (idx & 7) << 2;
            cp_async16(base + (uint32_t)(m * AS_STRIDE + k4) * 4,
                       xg + (size_t)m * CC + k4);
        }
        // B: 3 x 32 x 128 (pre-rounded tf32 bits)
        #pragma unroll
        for (int p = 0; p < 12; p++) {
            int idx = tid + p * 256;
            int w = idx >> 10;
            int rem = idx & 1023;
            int k = rem >> 5, n4 = (rem & 31) << 2;
            cp_async16(base + (uint32_t)(A_BUF + w * B_W_BUF + k * BS_STRIDE + n4) * 4,
                       g_w + (size_t)w * CC * HH + (size_t)(c * 32 + k) * HH + n4);
        }
        cp_async_commit();
    };

    issue_stage(0, 0);

    for (int c = 0; c < NCH; c++) {
        const int buf = c & 1;
        __syncthreads();
        if (c + 1 < NCH) {
            issue_stage(c + 1, buf ^ 1);
            cp_async_wait_1();
        } else {
            cp_async_wait_all();
        }
        __syncthreads();

        const uint32_t* As = sm_u + buf * STAGE_WORDS;
        const uint32_t* Bs = As + A_BUF;

        #pragma unroll
        for (int ks = 0; ks < 4; ks++) {
            const int k = ks * 8 + t;
            uint32_t afr[2][4];
            #pragma unroll
            for (int mt = 0; mt < 2; mt++) {
                int rbase = wr * 32 + mt * 16;
                afr[mt][0] = As[(rbase + g)     * AS_STRIDE + k];
                afr[mt][1] = As[(rbase + g + 8) * AS_STRIDE + k];
                afr[mt][2] = As[(rbase + g)     * AS_STRIDE + k + 4];
                afr[mt][3] = As[(rbase + g + 8) * AS_STRIDE + k + 4];
            }
            #pragma unroll
            for (int w = 0; w < 3; w++) {
                const uint32_t* Bw = Bs + w * B_W_BUF;
                #pragma unroll
                for (int nt = 0; nt < 8; nt++) {
                    const int n = wc * 64 + nt * 8 + g;
                    uint32_t bfr[2];
                    bfr[0] = Bw[k * BS_STRIDE + n];
                    bfr[1] = Bw[(k + 4) * BS_STRIDE + n];
                    mma8(acc[w][0][nt], afr[0], bfr);
                    mma8(acc[w][1][nt], afr[1], bfr);
                }
            }
        }
    }

    // ---- epilogue: store tf32-rounded bits ----
    float* outs[3] = {g_q, g_k, g_v};
    #pragma unroll
    for (int w = 0; w < 3; w++) {
        float* outw = outs[w];
        #pragma unroll
        for (int mt = 0; mt < 2; mt++) {
            int r0 = m0 + wr * 32 + mt * 16 + g;
            #pragma unroll
            for (int nt = 0; nt < 8; nt++) {
                int col = wc * 64 + nt * 8 + 2 * t;
                *reinterpret_cast<float2*>(&outw[(size_t)r0 * HH + col]) =
                    make_float2(__uint_as_float(f2tf(acc[w][mt][nt][0])),
                                __uint_as_float(f2tf(acc[w][mt][nt][1])));
                *reinterpret_cast<float2*>(&outw[(size_t)(r0 + 8) * HH + col]) =
                    make_float2(__uint_as_float(f2tf(acc[w][mt][nt][2])),
                                __uint_as_float(f2tf(acc[w][mt][nt][3])));
            }
        }
    }
}

// ===========================================================================
// Kernel 2: register-resident causal flash attention with cp.async pipeline
// (unchanged — known good at ~170 us).
// ===========================================================================
#define KS_STRIDE 132
#define VS_STRIDE 136
#define ATTN_SMEM ((64 * KS_STRIDE + 64 * VS_STRIDE) * 4)   // 68608 B

__global__ __launch_bounds__(128, 2) void attn_fa2_kernel(float* __restrict__ out)
{
    extern __shared__ float smf[];
    float* Ks = smf;                     // [64][132]
    float* Vs = Ks + 64 * KS_STRIDE;     // [64][136]  (also Q staging)
    uint32_t* Ksu = reinterpret_cast<uint32_t*>(Ks);
    uint32_t* Vsu = reinterpret_cast<uint32_t*>(Vs);
    const uint32_t Ks_a = smem_u32(Ks);
    const uint32_t Vs_a = smem_u32(Vs);

    const int b  = blockIdx.y;
    const int qt = (int)gridDim.x - 1 - (int)blockIdx.x;
    const int q0 = qt * 64;
    const int tid  = threadIdx.x;
    const int wid  = tid >> 5;
    const int lane = tid & 31;
    const int g = lane >> 2;
    const int t = lane & 3;

    const int r0l = wid * 16 + g;
    const int r1l = r0l + 8;

    const float* kbase = g_k + (size_t)b * TT * HH;
    const float* vbase = g_v + (size_t)b * TT * HH;

    {
        const float* kg = kbase;
        #pragma unroll
        for (int p = 0; p < 16; p++) {
            int idx = tid + p * 128;
            int r = idx >> 5, c = (idx & 31) << 2;
            cp_async16(Ks_a + (uint32_t)(r * KS_STRIDE + c) * 4,
                       kg + (size_t)r * HH + c);
        }
        cp_async_commit();
    }
    {
        const float* qg = g_q + ((size_t)b * TT + q0) * HH;
        #pragma unroll
        for (int p = 0; p < 16; p++) {
            int idx = tid + p * 128;
            int r = idx >> 5, c4 = (idx & 31) << 2;
            *reinterpret_cast<float4*>(&Vs[r * VS_STRIDE + c4]) =
                *reinterpret_cast<const float4*>(&qg[(size_t)r * HH + c4]);
        }
    }
    __syncthreads();

    uint32_t qfr[16][4];
    #pragma unroll
    for (int ks = 0; ks < 16; ks++) {
        const int k = ks * 8 + t;
        qfr[ks][0] = Vsu[r0l * VS_STRIDE + k];
        qfr[ks][1] = Vsu[r1l * VS_STRIDE + k];
        qfr[ks][2] = Vsu[r0l * VS_STRIDE + k + 4];
        qfr[ks][3] = Vsu[r1l * VS_STRIDE + k + 4];
    }

    float m0 = -INFINITY, m1 = -INFINITY, l0 = 0.0f, l1 = 0.0f;
    float oacc[16][4];
    #pragma unroll
    for (int nt = 0; nt < 16; nt++)
        #pragma unroll
        for (int e = 0; e < 4; e++) oacc[nt][e] = 0.0f;

    const uint32_t srcA = (lane & 28) | (t >> 1);
    const uint32_t srcB = srcA + 2;

    const int nkt = qt + 1;
    for (int kt = 0; kt < nkt; kt++) {
        cp_async_wait_all();
        __syncthreads();

        {
            const float* vg = vbase + (size_t)kt * 64 * HH;
            #pragma unroll
            for (int p = 0; p < 16; p++) {
                int idx = tid + p * 128;
                int r = idx >> 5, c = (idx & 31) << 2;
                cp_async16(Vs_a + (uint32_t)(r * VS_STRIDE + c) * 4,
                           vg + (size_t)r * HH + c);
            }
            cp_async_commit();
        }

        float sacc[8][4];
        #pragma unroll
        for (int nt = 0; nt < 8; nt++)
            #pragma unroll
            for (int e = 0; e < 4; e++) sacc[nt][e] = 0.0f;

        #pragma unroll
        for (int ks = 0; ks < 16; ks++) {
            const int k = ks * 8 + t;
            #pragma unroll
            for (int nt = 0; nt < 8; nt++) {
                const int n = nt * 8 + g;
                uint32_t bfr[2];
                bfr[0] = Ksu[n * KS_STRIDE + k];
                bfr[1] = Ksu[n * KS_STRIDE + k + 4];
                mma8(sacc[nt], qfr[ks], bfr);
            }
        }

        if (kt == qt) {
            #pragma unroll
            for (int nt = 0; nt < 8; nt++) {
                const int cl = nt * 8 + 2 * t;
                if (cl     > r0l) sacc[nt][0] = -INFINITY;
                if (cl + 1 > r0l) sacc[nt][1] = -INFINITY;
                if (cl     > r1l) sacc[nt][2] = -INFINITY;
                if (cl + 1 > r1l) sacc[nt][3] = -INFINITY;
            }
        }

        float mx0 = -INFINITY, mx1 = -INFINITY;
        #pragma unroll
        for (int nt = 0; nt < 8; nt++) {
            mx0 = fmaxf(mx0, fmaxf(sacc[nt][0], sacc[nt][1]));
            mx1 = fmaxf(mx1, fmaxf(sacc[nt][2], sacc[nt][3]));
        }
        mx0 = fmaxf(mx0, __shfl_xor_sync(0xffffffffu, mx0, 1));
        mx0 = fmaxf(mx0, __shfl_xor_sync(0xffffffffu, mx0, 2));
        mx1 = fmaxf(mx1, __shfl_xor_sync(0xffffffffu, mx1, 1));
        mx1 = fmaxf(mx1, __shfl_xor_sync(0xffffffffu, mx1, 2));

        const float m0n = fmaxf(m0, mx0);
        const float m1n = fmaxf(m1, mx1);
        const float c0 = __expf(m0 - m0n);
        const float c1 = __expf(m1 - m1n);

        float s0 = 0.0f, s1 = 0.0f;
        #pragma unroll
        for (int nt = 0; nt < 8; nt++) {
            sacc[nt][0] = __expf(sacc[nt][0] - m0n);
            sacc[nt][1] = __expf(sacc[nt][1] - m0n);
            sacc[nt][2] = __expf(sacc[nt][2] - m1n);
            sacc[nt][3] = __expf(sacc[nt][3] - m1n);
            s0 += sacc[nt][0] + sacc[nt][1];
            s1 += sacc[nt][2] + sacc[nt][3];
        }
        s0 += __shfl_xor_sync(0xffffffffu, s0, 1);
        s0 += __shfl_xor_sync(0xffffffffu, s0, 2);
        s1 += __shfl_xor_sync(0xffffffffu, s1, 1);
        s1 += __shfl_xor_sync(0xffffffffu, s1, 2);

        l0 = l0 * c0 + s0;
        l1 = l1 * c1 + s1;
        m0 = m0n;
        m1 = m1n;

        #pragma unroll
        for (int nt = 0; nt < 16; nt++) {
            oacc[nt][0] *= c0; oacc[nt][1] *= c0;
            oacc[nt][2] *= c1; oacc[nt][3] *= c1;
        }

        cp_async_wait_all();
        __syncthreads();

        if (kt + 1 < nkt) {
            const float* kg = kbase + (size_t)(kt + 1) * 64 * HH;
            #pragma unroll
            for (int p = 0; p < 16; p++) {
                int idx = tid + p * 128;
                int r = idx >> 5, c = (idx & 31) << 2;
                cp_async16(Ks_a + (uint32_t)(r * KS_STRIDE + c) * 4,
                           kg + (size_t)r * HH + c);
            }
            cp_async_commit();
        }

        #pragma unroll
        for (int kk = 0; kk < 8; kk++) {
            float v0 = __shfl_sync(0xffffffffu, sacc[kk][0], srcA);
            float v1 = __shfl_sync(0xffffffffu, sacc[kk][1], srcA);
            float v2 = __shfl_sync(0xffffffffu, sacc[kk][2], srcA);
            float v3 = __shfl_sync(0xffffffffu, sacc[kk][3], srcA);
            float w0 = __shfl_sync(0xffffffffu, sacc[kk][0], srcB);
            float w1 = __shfl_sync(0xffffffffu, sacc[kk][1], srcB);
            float w2 = __shfl_sync(0xffffffffu, sacc[kk][2], srcB);
            float w3 = __shfl_sync(0xffffffffu, sacc[kk][3], srcB);
            uint32_t afr[4];
            afr[0] = f2tf((t & 1) ? v1 : v0);
            afr[1] = f2tf((t & 1) ? v3 : v2);
            afr[2] = f2tf((t & 1) ? w1 : w0);
            afr[3] = f2tf((t & 1) ? w3 : w2);

            const int k = kk * 8 + t;
            #pragma unroll
            for (int nt = 0; nt < 16; nt++) {
                const int n = nt * 8 + g;
                uint32_t bfr[2];
                bfr[0] = Vsu[k * VS_STRIDE + n];
                bfr[1] = Vsu[(k + 4) * VS_STRIDE + n];
                mma8(oacc[nt], afr, bfr);
            }
        }
    }

    const float inv0 = 1.0f / l0;
    const float inv1 = 1.0f / l1;
    float* og = out + ((size_t)b * TT + q0) * HH;
    #pragma unroll
    for (int nt = 0; nt < 16; nt++) {
        const int col = nt * 8 + 2 * t;
        *reinterpret_cast<float2*>(&og[(size_t)r0l * HH + col]) =
            make_float2(oacc[nt][0] * inv0, oacc[nt][1] * inv0);
        *reinterpret_cast<float2*>(&og[(size_t)r1l * HH + col]) =
            make_float2(oacc[nt][2] * inv1, oacc[nt][3] * inv1);
    }
}

// ===========================================================================
// Launch
// ===========================================================================
extern "C" void kernel_launch(void* const* d_in, const int* in_sizes, int n_in,
                              void* d_out, int out_size)
{
    const float* x  = (const float*)d_in[0];
    const float* Wq = (const float*)d_in[1];
    const float* Wk = (const float*)d_in[2];
    const float* Wv = (const float*)d_in[3];
    float* out = (float*)d_out;

    cudaFuncSetAttribute(qkv_fused_kernel,
                         cudaFuncAttributeMaxDynamicSharedMemorySize, QKV_SMEM);
    cudaFuncSetAttribute(attn_fa2_kernel,
                         cudaFuncAttributeMaxDynamicSharedMemorySize, ATTN_SMEM);

    conv_w_kernel<<<96, 256>>>(Wq, Wk, Wv);
    qkv_fused_kernel<<<TT * BB / 128, 256, QKV_SMEM>>>(x);
    attn_fa2_kernel<<<dim3(TT / 64, BB), 128, ATTN_SMEM>>>(out);
}